// round 5
// baseline (speedup 1.0000x reference)
#include <cuda_runtime.h>
#include <math.h>

// Single working thread, pure scalar, zero shuffles.
// lambda_max(GG^T) ~ tr(M^16)^(1/16) = (||M^8||_F^2)^(1/16), 3 symmetric squarings.
// tanh via HW tanh.approx.f32; 16th root via lg2/ex2 approx MUFU.

__device__ __forceinline__ float htanh(float s) {
    float r;
    asm("tanh.approx.f32 %0, %1;" : "=f"(r) : "f"(s));
    return r;
}
__device__ __forceinline__ float ex2(float s) {
    float r;
    asm("ex2.approx.f32 %0, %1;" : "=f"(r) : "f"(s));
    return r;
}
__device__ __forceinline__ float lg2(float s) {
    float r;
    asm("lg2.approx.f32 %0, %1;" : "=f"(r) : "f"(s));
    return r;
}

// T = S*S for symmetric S (10 unique dots, mirrored)
__device__ __forceinline__ void sym_square(const float S[16], float T[16]) {
    #pragma unroll
    for (int i = 0; i < 4; i++) {
        #pragma unroll
        for (int j = i; j < 4; j++) {
            float s = 0.f;
            #pragma unroll
            for (int k = 0; k < 4; k++) s = fmaf(S[i*4+k], S[k*4+j], s);
            T[i*4+j] = s;
            T[j*4+i] = s;
        }
    }
}

__global__ void __launch_bounds__(32, 1)
kuramoto_kernel(const float* __restrict__ x,
                const float* __restrict__ Kp,
                const float* __restrict__ bp,
                const float* __restrict__ Gp,
                const float* __restrict__ adjp,
                float* __restrict__ out)
{
    if (threadIdx.x != 0) return;

    // ---- front-batched vector loads (single latency exposure) ----
    float4 xa = ((const float4*)x)[0];
    float4 xv = ((const float4*)x)[1];
    float4 xx = ((const float4*)x)[2];
    float4 Kr0 = ((const float4*)Kp)[0], Kr1 = ((const float4*)Kp)[1],
           Kr2 = ((const float4*)Kp)[2], Kr3 = ((const float4*)Kp)[3];
    float4 Gr0 = ((const float4*)Gp)[0], Gr1 = ((const float4*)Gp)[1],
           Gr2 = ((const float4*)Gp)[2], Gr3 = ((const float4*)Gp)[3];
    float4 Ar0 = ((const float4*)adjp)[0], Ar1 = ((const float4*)adjp)[1],
           Ar2 = ((const float4*)adjp)[2], Ar3 = ((const float4*)adjp)[3];
    float4 bb  = ((const float4*)bp)[0];

    float a[4]  = {xa.x, xa.y, xa.z, xa.w};
    float v[4]  = {xv.x, xv.y, xv.z, xv.w};
    float xi[4] = {xx.x, xx.y, xx.z, xx.w};
    float K[16] = {Kr0.x,Kr0.y,Kr0.z,Kr0.w, Kr1.x,Kr1.y,Kr1.z,Kr1.w,
                   Kr2.x,Kr2.y,Kr2.z,Kr2.w, Kr3.x,Kr3.y,Kr3.z,Kr3.w};
    float G[16] = {Gr0.x,Gr0.y,Gr0.z,Gr0.w, Gr1.x,Gr1.y,Gr1.z,Gr1.w,
                   Gr2.x,Gr2.y,Gr2.z,Gr2.w, Gr3.x,Gr3.y,Gr3.z,Gr3.w};
    float A[16] = {Ar0.x,Ar0.y,Ar0.z,Ar0.w, Ar1.x,Ar1.y,Ar1.z,Ar1.w,
                   Ar2.x,Ar2.y,Ar2.z,Ar2.w, Ar3.x,Ar3.y,Ar3.z,Ar3.w};
    float bv[4] = {bb.x, bb.y, bb.z, bb.w};

    // ---- gamma = 0.1 * tr(M^16)^(1/16), M = G G^T ----
    float M[16];
    #pragma unroll
    for (int i = 0; i < 4; i++) {
        #pragma unroll
        for (int j = i; j < 4; j++) {
            float s = 0.f;
            #pragma unroll
            for (int k = 0; k < 4; k++) s = fmaf(G[i*4+k], G[j*4+k], s);
            M[i*4+j] = s; M[j*4+i] = s;
        }
    }
    float M2[16], M4[16], M8[16];
    sym_square(M,  M2);
    sym_square(M2, M4);
    sym_square(M4, M8);
    // tr(M^16) = ||M^8||_F^2, 4 parallel accumulators
    float t0 = 0.f, t1a = 0.f, t2 = 0.f, t3 = 0.f;
    #pragma unroll
    for (int i = 0; i < 4; i++) {
        t0  = fmaf(M8[i*4+0], M8[i*4+0], t0);
        t1a = fmaf(M8[i*4+1], M8[i*4+1], t1a);
        t2  = fmaf(M8[i*4+2], M8[i*4+2], t2);
        t3  = fmaf(M8[i*4+3], M8[i*4+3], t3);
    }
    float tr16 = (t0 + t1a) + (t2 + t3);
    float gamma = 0.1f * ex2(lg2(tr16) * 0.0625f);

    // ---- dH = K^T tanh(K xi + b) ----
    float th[4];
    #pragma unroll
    for (int i = 0; i < 4; i++) {
        float s = bv[i];
        #pragma unroll
        for (int j = 0; j < 4; j++) s = fmaf(K[i*4+j], xi[j], s);
        th[i] = htanh(s);
    }
    float dH[4];
    #pragma unroll
    for (int i = 0; i < 4; i++) {
        float s = 0.f;
        #pragma unroll
        for (int j = 0; j < 4; j++) s = fmaf(K[j*4+i], th[j], s);
        dH[i] = s;
    }

    // ---- interactions (6 unique cos; diagonal term is exactly 0: v[j]-v[j]=0) ----
    float c01 = __cosf(a[0] - a[1]);
    float c02 = __cosf(a[0] - a[2]);
    float c03 = __cosf(a[0] - a[3]);
    float c12 = __cosf(a[1] - a[2]);
    float c13 = __cosf(a[1] - a[3]);
    float c23 = __cosf(a[2] - a[3]);

    float inter[4];
    // inter[j] = sum_{i != j} adj[i][j]*cos(a_j - a_i)*(v_j - v_i)
    inter[0] = fmaf(A[4]*c01,  v[0]-v[1],
               fmaf(A[8]*c02,  v[0]-v[2],
                    A[12]*c03*(v[0]-v[3])));
    inter[1] = fmaf(A[1]*c01,  v[1]-v[0],
               fmaf(A[9]*c12,  v[1]-v[2],
                    A[13]*c13*(v[1]-v[3])));
    inter[2] = fmaf(A[2]*c02,  v[2]-v[0],
               fmaf(A[6]*c12,  v[2]-v[1],
                    A[14]*c23*(v[2]-v[3])));
    inter[3] = fmaf(A[3]*c03,  v[3]-v[0],
               fmaf(A[7]*c13,  v[3]-v[1],
                    A[11]*c23*(v[3]-v[2])));

    // ---- AG = adj .* G ; dxdt = -1.25 * ((AG)^T dH) * inter ----
    float AG[16];
    #pragma unroll
    for (int i = 0; i < 16; i++) AG[i] = A[i] * G[i];

    float dxdt[4];
    #pragma unroll
    for (int i = 0; i < 4; i++) {
        float s = 0.f;
        #pragma unroll
        for (int j = 0; j < 4; j++) s = fmaf(AG[j*4+i], dH[j], s);
        dxdt[i] = -1.25f * s * inter[i];
    }

    // ---- dxi = (J - gamma I) dH + AG x2 ----
    float JdH[4];
    JdH[0] = fmaf(-gamma, dH[0], -dH[1]);
    JdH[1] = fmaf(-gamma, dH[1],  dH[0]);
    JdH[2] = fmaf(-gamma, dH[2], -dH[3]);
    JdH[3] = fmaf(-gamma, dH[3],  dH[2]);

    float dxi[4];
    #pragma unroll
    for (int i = 0; i < 4; i++) {
        float s = JdH[i];
        #pragma unroll
        for (int j = 0; j < 4; j++) s = fmaf(AG[i*4+j], v[j], s);
        dxi[i] = s;
    }

    // ---- stores ----
    float4* o4 = (float4*)out;
    o4[0] = make_float4(v[0], v[1], v[2], v[3]);
    o4[1] = make_float4(dxdt[0], dxdt[1], dxdt[2], dxdt[3]);
    o4[2] = make_float4(dxi[0], dxi[1], dxi[2], dxi[3]);
}

extern "C" void kernel_launch(void* const* d_in, const int* in_sizes, int n_in,
                              void* d_out, int out_size)
{
    // metadata order: t(1), x(12), K(16), b(4), G(16), adj(16)
    const float* x   = (const float*)d_in[1];
    const float* K   = (const float*)d_in[2];
    const float* b   = (const float*)d_in[3];
    const float* G   = (const float*)d_in[4];
    const float* adj = (const float*)d_in[5];
    float* out = (float*)d_out;

    kuramoto_kernel<<<1, 32>>>(x, K, b, G, adj, out);
}

// round 6
// speedup vs baseline: 1.3403x; 1.3403x over previous
#include <cuda_runtime.h>
#include <math.h>

// Single working thread, pure scalar, zero shuffles.
// lambda_max(GG^T) ~ tr(M^16)^(1/16) = (||M^8||_F^2)^(1/16), 3 symmetric squarings.
// Precise exp-based tanh (tanh.approx cost 40x rel_err in R5 for no speed win).

__device__ __forceinline__ float fast_tanh(float s) {
    float e = __expf(2.0f * s);
    return 1.0f - __fdividef(2.0f, e + 1.0f);
}
__device__ __forceinline__ float ex2(float s) {
    float r; asm("ex2.approx.f32 %0, %1;" : "=f"(r) : "f"(s)); return r;
}
__device__ __forceinline__ float lg2(float s) {
    float r; asm("lg2.approx.f32 %0, %1;" : "=f"(r) : "f"(s)); return r;
}

// T = S*S for symmetric S (10 unique dots, mirrored)
__device__ __forceinline__ void sym_square(const float S[16], float T[16]) {
    #pragma unroll
    for (int i = 0; i < 4; i++) {
        #pragma unroll
        for (int j = i; j < 4; j++) {
            float s = 0.f;
            #pragma unroll
            for (int k = 0; k < 4; k++) s = fmaf(S[i*4+k], S[k*4+j], s);
            T[i*4+j] = s;
            T[j*4+i] = s;
        }
    }
}

__global__ void __launch_bounds__(32, 1)
kuramoto_kernel(const float* __restrict__ x,
                const float* __restrict__ Kp,
                const float* __restrict__ bp,
                const float* __restrict__ Gp,
                const float* __restrict__ adjp,
                float* __restrict__ out)
{
    if (threadIdx.x != 0) return;

    // ---- front-batched vector loads (single latency exposure) ----
    float4 xa = ((const float4*)x)[0];
    float4 xv = ((const float4*)x)[1];
    float4 xx = ((const float4*)x)[2];
    float4 Kr0 = ((const float4*)Kp)[0], Kr1 = ((const float4*)Kp)[1],
           Kr2 = ((const float4*)Kp)[2], Kr3 = ((const float4*)Kp)[3];
    float4 Gr0 = ((const float4*)Gp)[0], Gr1 = ((const float4*)Gp)[1],
           Gr2 = ((const float4*)Gp)[2], Gr3 = ((const float4*)Gp)[3];
    float4 Ar0 = ((const float4*)adjp)[0], Ar1 = ((const float4*)adjp)[1],
           Ar2 = ((const float4*)adjp)[2], Ar3 = ((const float4*)adjp)[3];
    float4 bb  = ((const float4*)bp)[0];

    float a[4]  = {xa.x, xa.y, xa.z, xa.w};
    float v[4]  = {xv.x, xv.y, xv.z, xv.w};
    float xi[4] = {xx.x, xx.y, xx.z, xx.w};
    float K[16] = {Kr0.x,Kr0.y,Kr0.z,Kr0.w, Kr1.x,Kr1.y,Kr1.z,Kr1.w,
                   Kr2.x,Kr2.y,Kr2.z,Kr2.w, Kr3.x,Kr3.y,Kr3.z,Kr3.w};
    float G[16] = {Gr0.x,Gr0.y,Gr0.z,Gr0.w, Gr1.x,Gr1.y,Gr1.z,Gr1.w,
                   Gr2.x,Gr2.y,Gr2.z,Gr2.w, Gr3.x,Gr3.y,Gr3.z,Gr3.w};
    float A[16] = {Ar0.x,Ar0.y,Ar0.z,Ar0.w, Ar1.x,Ar1.y,Ar1.z,Ar1.w,
                   Ar2.x,Ar2.y,Ar2.z,Ar2.w, Ar3.x,Ar3.y,Ar3.z,Ar3.w};
    float bv[4] = {bb.x, bb.y, bb.z, bb.w};

    // ---- gamma = 0.1 * tr(M^16)^(1/16), M = G G^T ----
    float M[16];
    #pragma unroll
    for (int i = 0; i < 4; i++) {
        #pragma unroll
        for (int j = i; j < 4; j++) {
            float s = 0.f;
            #pragma unroll
            for (int k = 0; k < 4; k++) s = fmaf(G[i*4+k], G[j*4+k], s);
            M[i*4+j] = s; M[j*4+i] = s;
        }
    }
    float M2[16], M4[16], M8[16];
    sym_square(M,  M2);
    sym_square(M2, M4);
    sym_square(M4, M8);
    // tr(M^16) = ||M^8||_F^2, 4 parallel accumulators
    float t0 = 0.f, t1 = 0.f, t2 = 0.f, t3 = 0.f;
    #pragma unroll
    for (int i = 0; i < 4; i++) {
        t0 = fmaf(M8[i*4+0], M8[i*4+0], t0);
        t1 = fmaf(M8[i*4+1], M8[i*4+1], t1);
        t2 = fmaf(M8[i*4+2], M8[i*4+2], t2);
        t3 = fmaf(M8[i*4+3], M8[i*4+3], t3);
    }
    float tr16 = (t0 + t1) + (t2 + t3);
    float gamma = 0.1f * ex2(lg2(tr16) * 0.0625f);

    // ---- dH = K^T tanh(K xi + b) ----
    float th[4];
    #pragma unroll
    for (int i = 0; i < 4; i++) {
        float s = bv[i];
        #pragma unroll
        for (int j = 0; j < 4; j++) s = fmaf(K[i*4+j], xi[j], s);
        th[i] = fast_tanh(s);
    }
    float dH[4];
    #pragma unroll
    for (int i = 0; i < 4; i++) {
        float s = 0.f;
        #pragma unroll
        for (int j = 0; j < 4; j++) s = fmaf(K[j*4+i], th[j], s);
        dH[i] = s;
    }

    // ---- interactions: 6 unique cos; diagonal exactly 0 (v[j]-v[j]=0) ----
    float c01 = __cosf(a[0] - a[1]);
    float c02 = __cosf(a[0] - a[2]);
    float c03 = __cosf(a[0] - a[3]);
    float c12 = __cosf(a[1] - a[2]);
    float c13 = __cosf(a[1] - a[3]);
    float c23 = __cosf(a[2] - a[3]);

    float inter[4];
    // inter[j] = sum_{i != j} adj[i][j]*cos(a_j - a_i)*(v_j - v_i)
    inter[0] = fmaf(A[4]*c01,  v[0]-v[1],
               fmaf(A[8]*c02,  v[0]-v[2],
                    A[12]*c03*(v[0]-v[3])));
    inter[1] = fmaf(A[1]*c01,  v[1]-v[0],
               fmaf(A[9]*c12,  v[1]-v[2],
                    A[13]*c13*(v[1]-v[3])));
    inter[2] = fmaf(A[2]*c02,  v[2]-v[0],
               fmaf(A[6]*c12,  v[2]-v[1],
                    A[14]*c23*(v[2]-v[3])));
    inter[3] = fmaf(A[3]*c03,  v[3]-v[0],
               fmaf(A[7]*c13,  v[3]-v[1],
                    A[11]*c23*(v[3]-v[2])));

    // ---- AG = adj .* G ; dxdt = -1.25 * ((AG)^T dH) * inter ----
    float AG[16];
    #pragma unroll
    for (int i = 0; i < 16; i++) AG[i] = A[i] * G[i];

    float dxdt[4];
    #pragma unroll
    for (int i = 0; i < 4; i++) {
        float s = 0.f;
        #pragma unroll
        for (int j = 0; j < 4; j++) s = fmaf(AG[j*4+i], dH[j], s);
        dxdt[i] = -1.25f * s * inter[i];
    }

    // ---- dxi = (J - gamma I) dH + AG x2 (J part fused into init) ----
    float JdH[4];
    JdH[0] = fmaf(-gamma, dH[0], -dH[1]);
    JdH[1] = fmaf(-gamma, dH[1],  dH[0]);
    JdH[2] = fmaf(-gamma, dH[2], -dH[3]);
    JdH[3] = fmaf(-gamma, dH[3],  dH[2]);

    float dxi[4];
    #pragma unroll
    for (int i = 0; i < 4; i++) {
        float s = JdH[i];
        #pragma unroll
        for (int j = 0; j < 4; j++) s = fmaf(AG[i*4+j], v[j], s);
        dxi[i] = s;
    }

    // ---- stores ----
    float4* o4 = (float4*)out;
    o4[0] = make_float4(v[0], v[1], v[2], v[3]);
    o4[1] = make_float4(dxdt[0], dxdt[1], dxdt[2], dxdt[3]);
    o4[2] = make_float4(dxi[0], dxi[1], dxi[2], dxi[3]);
}

extern "C" void kernel_launch(void* const* d_in, const int* in_sizes, int n_in,
                              void* d_out, int out_size)
{
    // metadata order: t(1), x(12), K(16), b(4), G(16), adj(16)
    const float* x   = (const float*)d_in[1];
    const float* K   = (const float*)d_in[2];
    const float* b   = (const float*)d_in[3];
    const float* G   = (const float*)d_in[4];
    const float* adj = (const float*)d_in[5];
    float* out = (float*)d_out;

    kuramoto_kernel<<<1, 32>>>(x, K, b, G, adj, out);
}

// round 7
// speedup vs baseline: 1.3497x; 1.0070x over previous
#include <cuda_runtime.h>
#include <math.h>

// Single working thread, pure scalar, zero shuffles. Converged structure:
// - lambda_max(GG^T) ~ tr(M^16)^(1/16) = (||M^8||_F^2)^(1/16), 3 symmetric squarings
// - precise exp-based tanh (tanh.approx costs 40x rel_err for zero speed win)
// - 6 unique cosines, diagonal of interaction sum exactly zero
// - velocity differences CSE'd (6 instead of 12)
// Bench total is pinned at the single-launch graph-replay floor (~4.6us);
// kernel compute (~0.6us) << per-launch overhead (~3us, T_ovh).

__device__ __forceinline__ float fast_tanh(float s) {
    float e = __expf(2.0f * s);
    return 1.0f - __fdividef(2.0f, e + 1.0f);
}
__device__ __forceinline__ float ex2(float s) {
    float r; asm("ex2.approx.f32 %0, %1;" : "=f"(r) : "f"(s)); return r;
}
__device__ __forceinline__ float lg2(float s) {
    float r; asm("lg2.approx.f32 %0, %1;" : "=f"(r) : "f"(s)); return r;
}

// T = S*S for symmetric S (10 unique dots, mirrored)
__device__ __forceinline__ void sym_square(const float S[16], float T[16]) {
    #pragma unroll
    for (int i = 0; i < 4; i++) {
        #pragma unroll
        for (int j = i; j < 4; j++) {
            float s = 0.f;
            #pragma unroll
            for (int k = 0; k < 4; k++) s = fmaf(S[i*4+k], S[k*4+j], s);
            T[i*4+j] = s;
            T[j*4+i] = s;
        }
    }
}

__global__ void __launch_bounds__(32, 1)
kuramoto_kernel(const float* __restrict__ x,
                const float* __restrict__ Kp,
                const float* __restrict__ bp,
                const float* __restrict__ Gp,
                const float* __restrict__ adjp,
                float* __restrict__ out)
{
    if (threadIdx.x != 0) return;

    // ---- front-batched vector loads (single latency exposure) ----
    float4 xa = ((const float4*)x)[0];
    float4 xv = ((const float4*)x)[1];
    float4 xx = ((const float4*)x)[2];
    float4 Kr0 = ((const float4*)Kp)[0], Kr1 = ((const float4*)Kp)[1],
           Kr2 = ((const float4*)Kp)[2], Kr3 = ((const float4*)Kp)[3];
    float4 Gr0 = ((const float4*)Gp)[0], Gr1 = ((const float4*)Gp)[1],
           Gr2 = ((const float4*)Gp)[2], Gr3 = ((const float4*)Gp)[3];
    float4 Ar0 = ((const float4*)adjp)[0], Ar1 = ((const float4*)adjp)[1],
           Ar2 = ((const float4*)adjp)[2], Ar3 = ((const float4*)adjp)[3];
    float4 bb  = ((const float4*)bp)[0];

    float a[4]  = {xa.x, xa.y, xa.z, xa.w};
    float v[4]  = {xv.x, xv.y, xv.z, xv.w};
    float xi[4] = {xx.x, xx.y, xx.z, xx.w};
    float K[16] = {Kr0.x,Kr0.y,Kr0.z,Kr0.w, Kr1.x,Kr1.y,Kr1.z,Kr1.w,
                   Kr2.x,Kr2.y,Kr2.z,Kr2.w, Kr3.x,Kr3.y,Kr3.z,Kr3.w};
    float G[16] = {Gr0.x,Gr0.y,Gr0.z,Gr0.w, Gr1.x,Gr1.y,Gr1.z,Gr1.w,
                   Gr2.x,Gr2.y,Gr2.z,Gr2.w, Gr3.x,Gr3.y,Gr3.z,Gr3.w};
    float A[16] = {Ar0.x,Ar0.y,Ar0.z,Ar0.w, Ar1.x,Ar1.y,Ar1.z,Ar1.w,
                   Ar2.x,Ar2.y,Ar2.z,Ar2.w, Ar3.x,Ar3.y,Ar3.z,Ar3.w};
    float bv[4] = {bb.x, bb.y, bb.z, bb.w};

    // ---- gamma = 0.1 * tr(M^16)^(1/16), M = G G^T ----
    float M[16];
    #pragma unroll
    for (int i = 0; i < 4; i++) {
        #pragma unroll
        for (int j = i; j < 4; j++) {
            float s = 0.f;
            #pragma unroll
            for (int k = 0; k < 4; k++) s = fmaf(G[i*4+k], G[j*4+k], s);
            M[i*4+j] = s; M[j*4+i] = s;
        }
    }
    float M2[16], M4[16], M8[16];
    sym_square(M,  M2);
    sym_square(M2, M4);
    sym_square(M4, M8);
    // tr(M^16) = ||M^8||_F^2, 4 parallel accumulators
    float t0 = 0.f, t1 = 0.f, t2 = 0.f, t3 = 0.f;
    #pragma unroll
    for (int i = 0; i < 4; i++) {
        t0 = fmaf(M8[i*4+0], M8[i*4+0], t0);
        t1 = fmaf(M8[i*4+1], M8[i*4+1], t1);
        t2 = fmaf(M8[i*4+2], M8[i*4+2], t2);
        t3 = fmaf(M8[i*4+3], M8[i*4+3], t3);
    }
    float tr16 = (t0 + t1) + (t2 + t3);
    float gamma = 0.1f * ex2(lg2(tr16) * 0.0625f);

    // ---- dH = K^T tanh(K xi + b) ----
    float th[4];
    #pragma unroll
    for (int i = 0; i < 4; i++) {
        float s = bv[i];
        #pragma unroll
        for (int j = 0; j < 4; j++) s = fmaf(K[i*4+j], xi[j], s);
        th[i] = fast_tanh(s);
    }
    float dH[4];
    #pragma unroll
    for (int i = 0; i < 4; i++) {
        float s = 0.f;
        #pragma unroll
        for (int j = 0; j < 4; j++) s = fmaf(K[j*4+i], th[j], s);
        dH[i] = s;
    }

    // ---- interactions: 6 unique cos, 6 unique velocity diffs (CSE) ----
    float c01 = __cosf(a[0] - a[1]);
    float c02 = __cosf(a[0] - a[2]);
    float c03 = __cosf(a[0] - a[3]);
    float c12 = __cosf(a[1] - a[2]);
    float c13 = __cosf(a[1] - a[3]);
    float c23 = __cosf(a[2] - a[3]);
    float v01 = v[0] - v[1], v02 = v[0] - v[2], v03 = v[0] - v[3];
    float v12 = v[1] - v[2], v13 = v[1] - v[3], v23 = v[2] - v[3];

    // inter[j] = sum_{i != j} adj[i][j]*cos(a_j - a_i)*(v_j - v_i)
    // (reverse-direction terms use negated A*c coefficient with same diff)
    float inter[4];
    inter[0] = fmaf( A[4]*c01,  v01, fmaf( A[8]*c02,  v02,  A[12]*c03 * v03));
    inter[1] = fmaf(-A[1]*c01,  v01, fmaf( A[9]*c12,  v12,  A[13]*c13 * v13));
    inter[2] = fmaf(-A[2]*c02,  v02, fmaf(-A[6]*c12,  v12,  A[14]*c23 * v23));
    inter[3] = fmaf(-A[3]*c03,  v03, fmaf(-A[7]*c13,  v13, -A[11]*c23 * v23));

    // ---- AG = adj .* G ; dxdt = -1.25 * ((AG)^T dH) * inter ----
    float AG[16];
    #pragma unroll
    for (int i = 0; i < 16; i++) AG[i] = A[i] * G[i];

    float dxdt[4];
    #pragma unroll
    for (int i = 0; i < 4; i++) {
        float s = 0.f;
        #pragma unroll
        for (int j = 0; j < 4; j++) s = fmaf(AG[j*4+i], dH[j], s);
        dxdt[i] = -1.25f * s * inter[i];
    }

    // ---- dxi = (J - gamma I) dH + AG x2 (J part fused into accumulator init) ----
    float JdH[4];
    JdH[0] = fmaf(-gamma, dH[0], -dH[1]);
    JdH[1] = fmaf(-gamma, dH[1],  dH[0]);
    JdH[2] = fmaf(-gamma, dH[2], -dH[3]);
    JdH[3] = fmaf(-gamma, dH[3],  dH[2]);

    float dxi[4];
    #pragma unroll
    for (int i = 0; i < 4; i++) {
        float s = JdH[i];
        #pragma unroll
        for (int j = 0; j < 4; j++) s = fmaf(AG[i*4+j], v[j], s);
        dxi[i] = s;
    }

    // ---- stores ----
    float4* o4 = (float4*)out;
    o4[0] = make_float4(v[0], v[1], v[2], v[3]);
    o4[1] = make_float4(dxdt[0], dxdt[1], dxdt[2], dxdt[3]);
    o4[2] = make_float4(dxi[0], dxi[1], dxi[2], dxi[3]);
}

extern "C" void kernel_launch(void* const* d_in, const int* in_sizes, int n_in,
                              void* d_out, int out_size)
{
    // metadata order: t(1), x(12), K(16), b(4), G(16), adj(16)
    const float* x   = (const float*)d_in[1];
    const float* K   = (const float*)d_in[2];
    const float* b   = (const float*)d_in[3];
    const float* G   = (const float*)d_in[4];
    const float* adj = (const float*)d_in[5];
    float* out = (float*)d_out;

    kuramoto_kernel<<<1, 32>>>(x, K, b, G, adj, out);
}